// round 2
// baseline (speedup 1.0000x reference)
#include <cuda_runtime.h>

// ---------------------------------------------------------------------------
// KNNGaussianBlur: out = GaussianBlur_sigma4_radius12(img[0]) with replicate
// padding. The reference's /max ... *max cancels (conv is linear), so the max
// reduction is skipped entirely.
//
// Two-pass separable blur:
//   pass V: img -> g_scratch   (vertical 25-tap, row clamp = replicate pad)
//   pass H: g_scratch -> out   (horizontal 25-tap, col clamp = replicate pad)
// ---------------------------------------------------------------------------

#define H_IMG 4096
#define W_IMG 4096
#define C_IMG 3
#define RADIUS 12

// 201 MB scratch as device global (allocation inside kernel_launch is banned).
__device__ float g_scratch[(size_t)C_IMG * H_IMG * W_IMG];

// 13 unique weights of the symmetric 25-tap Gaussian, sigma=4, truncated at
// 3*sigma, normalized. Compile-time constants -> FFMA with immediate operand
// (rt_SMSP=1 on sm_103a, 2x throughput vs 3-reg FFMA).
__device__ constexpr float KW[13] = {
    0.09990835f, 0.09683452f, 0.08816879f, 0.07541476f, 0.06059747f,
    0.04574137f, 0.03243549f, 0.02160670f, 0.01352113f, 0.00794866f,
    0.00438966f, 0.00227733f, 0.00110988f
};

// Copy for dynamically-indexed access in the rare edge-thread path.
__constant__ float KW_c[13] = {
    0.09990835f, 0.09683452f, 0.08816879f, 0.07541476f, 0.06059747f,
    0.04574137f, 0.03243549f, 0.02160670f, 0.01352113f, 0.00794866f,
    0.00438966f, 0.00227733f, 0.00110988f
};

// ------------------------------ Vertical pass ------------------------------
// Each thread owns one float4 column and produces VROWS consecutive output
// rows. Loads VROWS + 24 input rows (2.5x raw amplification; vertical-halo
// overlap between adjacent blocks is caught by L2). Row clamping implements
// replicate padding uniformly (no divergence).
constexpr int VROWS = 16;

__global__ __launch_bounds__(128)
void vblur_kernel(const float4* __restrict__ in) {
    const int W4 = W_IMG / 4;                      // 1024 float4 per row
    int col4 = blockIdx.x * 128 + threadIdx.x;     // 0..1023
    int y0   = blockIdx.y * VROWS;
    int cch  = blockIdx.z;

    const float4* inc  = in + (size_t)cch * ((size_t)H_IMG * W4);
    float4*       outc = (float4*)g_scratch + (size_t)cch * ((size_t)H_IMG * W4);

    float4 acc[VROWS];
#pragma unroll
    for (int i = 0; i < VROWS; ++i) acc[i] = make_float4(0.f, 0.f, 0.f, 0.f);

#pragma unroll
    for (int rr = 0; rr < VROWS + 2 * RADIUS; ++rr) {
        int row = y0 - RADIUS + rr;
        row = row < 0 ? 0 : (row > H_IMG - 1 ? H_IMG - 1 : row);
        float4 v = __ldg(&inc[(size_t)row * W4 + col4]);
#pragma unroll
        for (int i = 0; i < VROWS; ++i) {
            constexpr int R = RADIUS;
            int d = rr - R - i;                    // compile-time per (rr,i)
            if (d >= -R && d <= R) {
                float w = KW[d < 0 ? -d : d];
                acc[i].x = fmaf(v.x, w, acc[i].x);
                acc[i].y = fmaf(v.y, w, acc[i].y);
                acc[i].z = fmaf(v.z, w, acc[i].z);
                acc[i].w = fmaf(v.w, w, acc[i].w);
            }
        }
    }

#pragma unroll
    for (int i = 0; i < VROWS; ++i)
        outc[(size_t)(y0 + i) * W4 + col4] = acc[i];
}

// ----------------------------- Horizontal pass -----------------------------
// Each thread produces HOUT=16 consecutive pixels of one row. Interior
// threads read 10 aligned float4 (x0-12 is a multiple of 4 since x0 = 16*t),
// streaming them through 16 scalar accumulators with constant weights.
// The two boundary threads per row take a scalar clamped path.
constexpr int HOUT = 16;

__global__ __launch_bounds__(256)
void hblur_kernel(float* __restrict__ out) {
    int row = blockIdx.x;
    int cch = blockIdx.y;
    int t   = threadIdx.x;                         // 0..255, covers one row
    int x0  = t * HOUT;

    size_t base = (size_t)cch * ((size_t)H_IMG * W_IMG) + (size_t)row * W_IMG;
    const float* inr = g_scratch + base;

    float acc[HOUT];
#pragma unroll
    for (int i = 0; i < HOUT; ++i) acc[i] = 0.f;

    if (x0 >= RADIUS && x0 + HOUT - 1 + RADIUS < W_IMG) {
        const float4* p = (const float4*)(inr + x0 - RADIUS);
#pragma unroll
        for (int j = 0; j < (HOUT + 2 * RADIUS) / 4; ++j) {   // 10 loads
            float4 v = __ldg(&p[j]);
#pragma unroll
            for (int e = 0; e < 4; ++e) {
                int rel = j * 4 + e - RADIUS;                 // -12 .. 27
                float vv = (e == 0) ? v.x : (e == 1) ? v.y : (e == 2) ? v.z : v.w;
#pragma unroll
                for (int i = 0; i < HOUT; ++i) {
                    constexpr int R = RADIUS;
                    int d = rel - i;                          // compile-time
                    if (d >= -R && d <= R)
                        acc[i] = fmaf(vv, KW[d < 0 ? -d : d], acc[i]);
                }
            }
        }
    } else {
        // Edge threads (x0==0 or x0==W-16): scalar, clamped (replicate pad).
        for (int i = 0; i < HOUT; ++i) {
            float a = 0.f;
            for (int d = -RADIUS; d <= RADIUS; ++d) {
                int xx = x0 + i + d;
                xx = xx < 0 ? 0 : (xx > W_IMG - 1 ? W_IMG - 1 : xx);
                a = fmaf(inr[xx], KW_c[d < 0 ? -d : d], a);
            }
            acc[i] = a;
        }
    }

#pragma unroll
    for (int i = 0; i < HOUT; i += 4) {
        float4 o = make_float4(acc[i], acc[i + 1], acc[i + 2], acc[i + 3]);
        *(float4*)(out + base + x0 + i) = o;
    }
}

// ------------------------------ entry point --------------------------------
extern "C" void kernel_launch(void* const* d_in, const int* in_sizes, int n_in,
                              void* d_out, int out_size) {
    const float* img = (const float*)d_in[0];      // [1,3,4096,4096] fp32
    float* out = (float*)d_out;                    // [3,4096,4096] fp32

    dim3 vgrid(W_IMG / 4 / 128, H_IMG / VROWS, C_IMG);   // (8, 256, 3)
    vblur_kernel<<<vgrid, 128>>>((const float4*)img);

    dim3 hgrid(H_IMG, C_IMG);                            // (4096, 3)
    hblur_kernel<<<hgrid, 256>>>(out);
}

// round 3
// speedup vs baseline: 1.4996x; 1.4996x over previous
#include <cuda_runtime.h>

// ---------------------------------------------------------------------------
// KNNGaussianBlur: out = GaussianBlur_sigma4_radius12(img[0]) with replicate
// padding. The reference's /max ... *max cancels (conv is linear), so the max
// reduction is skipped entirely.
//
// Two-pass separable blur:
//   pass V: img -> g_scratch   (vertical 25-tap, row clamp = replicate pad)
//   pass H: g_scratch -> out   (horizontal 25-tap, col clamp = replicate pad)
//
// R2 fix: hblur edge path is now fully unrolled. In R1 the un-unrolled edge
// loop dynamically indexed acc[] -> the whole array was demoted to local
// memory (regs=32, L1=59.5%, ALU=59.5% in ncu) -> 184us. With constant
// indices acc[] lives in registers and KW folds to FFMA immediates.
// ---------------------------------------------------------------------------

#define H_IMG 4096
#define W_IMG 4096
#define C_IMG 3
#define RADIUS 12

// 201 MB scratch as device global (allocation inside kernel_launch is banned).
__device__ float g_scratch[(size_t)C_IMG * H_IMG * W_IMG];

// 13 unique weights of the symmetric 25-tap Gaussian, sigma=4, truncated at
// 3*sigma, normalized. Compile-time constants -> FFMA with immediate operand
// (rt_SMSP=1 on sm_103a, 2x throughput vs 3-reg FFMA).
__device__ constexpr float KW[13] = {
    0.09990835f, 0.09683452f, 0.08816879f, 0.07541476f, 0.06059747f,
    0.04574137f, 0.03243549f, 0.02160670f, 0.01352113f, 0.00794866f,
    0.00438966f, 0.00227733f, 0.00110988f
};

// ------------------------------ Vertical pass ------------------------------
// Each thread owns one float4 column and produces VROWS consecutive output
// rows. Loads VROWS + 24 input rows (2.5x raw amplification; vertical-halo
// overlap between adjacent blocks is caught by L2). Row clamping implements
// replicate padding uniformly (no divergence). Measured 66us (~memory roof).
constexpr int VROWS = 16;

__global__ __launch_bounds__(128)
void vblur_kernel(const float4* __restrict__ in) {
    const int W4 = W_IMG / 4;                      // 1024 float4 per row
    int col4 = blockIdx.x * 128 + threadIdx.x;     // 0..1023
    int y0   = blockIdx.y * VROWS;
    int cch  = blockIdx.z;

    const float4* inc  = in + (size_t)cch * ((size_t)H_IMG * W4);
    float4*       outc = (float4*)g_scratch + (size_t)cch * ((size_t)H_IMG * W4);

    float4 acc[VROWS];
#pragma unroll
    for (int i = 0; i < VROWS; ++i) acc[i] = make_float4(0.f, 0.f, 0.f, 0.f);

#pragma unroll
    for (int rr = 0; rr < VROWS + 2 * RADIUS; ++rr) {
        int row = y0 - RADIUS + rr;
        row = row < 0 ? 0 : (row > H_IMG - 1 ? H_IMG - 1 : row);
        float4 v = __ldg(&inc[(size_t)row * W4 + col4]);
#pragma unroll
        for (int i = 0; i < VROWS; ++i) {
            constexpr int R = RADIUS;
            int d = rr - R - i;                    // compile-time per (rr,i)
            if (d >= -R && d <= R) {
                float w = KW[d < 0 ? -d : d];
                acc[i].x = fmaf(v.x, w, acc[i].x);
                acc[i].y = fmaf(v.y, w, acc[i].y);
                acc[i].z = fmaf(v.z, w, acc[i].z);
                acc[i].w = fmaf(v.w, w, acc[i].w);
            }
        }
    }

#pragma unroll
    for (int i = 0; i < VROWS; ++i)
        outc[(size_t)(y0 + i) * W4 + col4] = acc[i];
}

// ----------------------------- Horizontal pass -----------------------------
// Each thread produces HOUT=16 consecutive pixels of one row. Interior
// threads read 10 aligned float4 (x0-12 is a multiple of 4 since x0 = 16*t),
// streaming them through 16 scalar accumulators with constant weights.
// The two boundary threads per row (t=0, t=255) take a FULLY UNROLLED clamped
// path so acc[] stays registerized (see header comment).
constexpr int HOUT = 16;

__global__ __launch_bounds__(256)
void hblur_kernel(float* __restrict__ out) {
    int row = blockIdx.x;
    int cch = blockIdx.y;
    int t   = threadIdx.x;                         // 0..255, covers one row
    int x0  = t * HOUT;

    size_t base = (size_t)cch * ((size_t)H_IMG * W_IMG) + (size_t)row * W_IMG;
    const float* inr = g_scratch + base;

    float acc[HOUT];
#pragma unroll
    for (int i = 0; i < HOUT; ++i) acc[i] = 0.f;

    if (x0 >= RADIUS && x0 + HOUT - 1 + RADIUS < W_IMG) {
        const float4* p = (const float4*)(inr + x0 - RADIUS);
#pragma unroll
        for (int j = 0; j < (HOUT + 2 * RADIUS) / 4; ++j) {   // 10 loads
            float4 v = __ldg(&p[j]);
#pragma unroll
            for (int e = 0; e < 4; ++e) {
                int rel = j * 4 + e - RADIUS;                 // -12 .. 27
                float vv = (e == 0) ? v.x : (e == 1) ? v.y : (e == 2) ? v.z : v.w;
#pragma unroll
                for (int i = 0; i < HOUT; ++i) {
                    constexpr int R = RADIUS;
                    int d = rel - i;                          // compile-time
                    if (d >= -R && d <= R)
                        acc[i] = fmaf(vv, KW[d < 0 ? -d : d], acc[i]);
                }
            }
        }
    } else {
        // Edge threads (x0==0 or x0==W-16): clamped replicate padding.
        // FULLY UNROLLED so acc[] and KW[] indices are compile-time constant.
#pragma unroll
        for (int i = 0; i < HOUT; ++i) {
            float a = 0.f;
#pragma unroll
            for (int d = -RADIUS; d <= RADIUS; ++d) {
                int xx = x0 + i + d;
                xx = xx < 0 ? 0 : (xx > W_IMG - 1 ? W_IMG - 1 : xx);
                constexpr int R = RADIUS;  // keep KW index a constant expr
                a = fmaf(__ldg(&inr[xx]), KW[d < 0 ? -d : d], a);
                (void)R;
            }
            acc[i] = a;
        }
    }

#pragma unroll
    for (int i = 0; i < HOUT; i += 4) {
        float4 o = make_float4(acc[i], acc[i + 1], acc[i + 2], acc[i + 3]);
        *(float4*)(out + base + x0 + i) = o;
    }
}

// ------------------------------ entry point --------------------------------
extern "C" void kernel_launch(void* const* d_in, const int* in_sizes, int n_in,
                              void* d_out, int out_size) {
    const float* img = (const float*)d_in[0];      // [1,3,4096,4096] fp32
    float* out = (float*)d_out;                    // [3,4096,4096] fp32

    dim3 vgrid(W_IMG / 4 / 128, H_IMG / VROWS, C_IMG);   // (8, 256, 3)
    vblur_kernel<<<vgrid, 128>>>((const float4*)img);

    dim3 hgrid(H_IMG, C_IMG);                            // (4096, 3)
    hblur_kernel<<<hgrid, 256>>>(out);
}

// round 4
// speedup vs baseline: 1.6405x; 1.0939x over previous
#include <cuda_runtime.h>

// ---------------------------------------------------------------------------
// KNNGaussianBlur: out = GaussianBlur_sigma4_radius12(img[0]) with replicate
// padding. The reference's /max ... *max cancels (conv is linear), so the max
// reduction is skipped entirely.
//
// Two-pass separable blur:
//   pass V: img -> g_scratch   (vertical 25-tap, row clamp = replicate pad)
//   pass H: g_scratch -> out   (horizontal 25-tap, col clamp = replicate pad)
//
// R3 fix: hblur ownership is interleaved. In R2 lane t owned 16 CONSECUTIVE
// pixels (x0=16t) -> adjacent lanes' loads were 64B apart -> every LDG.128 /
// STG.128 touched 16 cache lines (16 L1 wavefronts vs ideal 4) -> L1=80.5%
// bound at 99.8us. Now lane t owns float4 columns {32g+t} of a 512-px warp
// chunk: all loads and stores are consecutive-across-lanes -> 4 wf/inst.
// ---------------------------------------------------------------------------

#define H_IMG 4096
#define W_IMG 4096
#define C_IMG 3
#define RADIUS 12

// 201 MB scratch as device global (allocation inside kernel_launch is banned).
__device__ float g_scratch[(size_t)C_IMG * H_IMG * W_IMG];

// 13 unique weights of the symmetric 25-tap Gaussian, sigma=4, truncated at
// 3*sigma, normalized. Compile-time constants -> FFMA with immediate operand
// (rt_SMSP=1 on sm_103a, 2x throughput vs 3-reg FFMA).
__device__ constexpr float KW[13] = {
    0.09990835f, 0.09683452f, 0.08816879f, 0.07541476f, 0.06059747f,
    0.04574137f, 0.03243549f, 0.02160670f, 0.01352113f, 0.00794866f,
    0.00438966f, 0.00227733f, 0.00110988f
};

// ------------------------------ Vertical pass ------------------------------
// Each thread owns one float4 column and produces VROWS consecutive output
// rows. Measured 66us (~memory roof for 402MB+halo traffic). Unchanged.
constexpr int VROWS = 16;

__global__ __launch_bounds__(128)
void vblur_kernel(const float4* __restrict__ in) {
    const int W4 = W_IMG / 4;                      // 1024 float4 per row
    int col4 = blockIdx.x * 128 + threadIdx.x;     // 0..1023
    int y0   = blockIdx.y * VROWS;
    int cch  = blockIdx.z;

    const float4* inc  = in + (size_t)cch * ((size_t)H_IMG * W4);
    float4*       outc = (float4*)g_scratch + (size_t)cch * ((size_t)H_IMG * W4);

    float4 acc[VROWS];
#pragma unroll
    for (int i = 0; i < VROWS; ++i) acc[i] = make_float4(0.f, 0.f, 0.f, 0.f);

#pragma unroll
    for (int rr = 0; rr < VROWS + 2 * RADIUS; ++rr) {
        int row = y0 - RADIUS + rr;
        row = row < 0 ? 0 : (row > H_IMG - 1 ? H_IMG - 1 : row);
        float4 v = __ldg(&inc[(size_t)row * W4 + col4]);
#pragma unroll
        for (int i = 0; i < VROWS; ++i) {
            constexpr int R = RADIUS;
            int d = rr - R - i;                    // compile-time per (rr,i)
            if (d >= -R && d <= R) {
                float w = KW[d < 0 ? -d : d];
                acc[i].x = fmaf(v.x, w, acc[i].x);
                acc[i].y = fmaf(v.y, w, acc[i].y);
                acc[i].z = fmaf(v.z, w, acc[i].z);
                acc[i].w = fmaf(v.w, w, acc[i].w);
            }
        }
    }

#pragma unroll
    for (int i = 0; i < VROWS; ++i)
        outc[(size_t)(y0 + i) * W4 + col4] = acc[i];
}

// ----------------------------- Horizontal pass -----------------------------
// Block = 256 threads = 8 warps = one full 4096-px row. Warp w owns the
// 512-px chunk [512w, 512w+512). Within it, lane t owns float4 columns
// {128w + 32g + t : g = 0..3}. For each group g the warp issues 7 coalesced
// LDG.128 (halo window, consecutive f4 across lanes) and 1 coalesced STG.128.
// Replicate padding: out-of-range f4 indices are fully out of the image
// (fi<0 -> all 4 elems clamp to x=0; fi>1023 -> all clamp to x=4095), so a
// broadcast of the edge pixel is exact.
__global__ __launch_bounds__(256)
void hblur_kernel(float* __restrict__ out) {
    const int W4 = W_IMG / 4;                      // 1024
    int row  = blockIdx.x;
    int cch  = blockIdx.y;
    int w    = threadIdx.x >> 5;                   // warp 0..7
    int lane = threadIdx.x & 31;

    size_t base = (size_t)cch * ((size_t)H_IMG * W_IMG) + (size_t)row * W_IMG;
    const float*  inr = g_scratch + base;
    const float4* in4 = (const float4*)inr;
    float4*       o4  = (float4*)(out + base);

#pragma unroll
    for (int g = 0; g < 4; ++g) {
        int fb = 128 * w + 32 * g + lane;          // this lane's output f4 col
        // Load 7 f4 covering floats [4*fb-12, 4*fb+15] (window for 4 outputs)
        float4 x[7];
#pragma unroll
        for (int j = 0; j < 7; ++j) {
            int fi = fb - 3 + j;
            float4 v;
            if (fi >= 0 && fi < W4) {
                v = __ldg(&in4[fi]);
            } else {
                float s = __ldg(&inr[fi < 0 ? 0 : W_IMG - 1]);
                v = make_float4(s, s, s, s);
            }
            x[j] = v;
        }
        // 4 outputs i=0..3 at positions 4*fb+i; input element (j,e) sits at
        // relative offset rel = 4j+e-12 from output i=0. Tap d = rel - i.
        float4 a = make_float4(0.f, 0.f, 0.f, 0.f);
#pragma unroll
        for (int j = 0; j < 7; ++j) {
#pragma unroll
            for (int e = 0; e < 4; ++e) {
                int rel = 4 * j + e - RADIUS;      // -12 .. 15, compile-time
                float xv = (e == 0) ? x[j].x : (e == 1) ? x[j].y
                         : (e == 2) ? x[j].z : x[j].w;
                {
                    int d = rel - 0;
                    if (d >= -RADIUS && d <= RADIUS)
                        a.x = fmaf(xv, KW[d < 0 ? -d : d], a.x);
                }
                {
                    int d = rel - 1;
                    if (d >= -RADIUS && d <= RADIUS)
                        a.y = fmaf(xv, KW[d < 0 ? -d : d], a.y);
                }
                {
                    int d = rel - 2;
                    if (d >= -RADIUS && d <= RADIUS)
                        a.z = fmaf(xv, KW[d < 0 ? -d : d], a.z);
                }
                {
                    int d = rel - 3;
                    if (d >= -RADIUS && d <= RADIUS)
                        a.w = fmaf(xv, KW[d < 0 ? -d : d], a.w);
                }
            }
        }
        o4[fb] = a;                                 // coalesced across lanes
    }
}

// ------------------------------ entry point --------------------------------
extern "C" void kernel_launch(void* const* d_in, const int* in_sizes, int n_in,
                              void* d_out, int out_size) {
    const float* img = (const float*)d_in[0];      // [1,3,4096,4096] fp32
    float* out = (float*)d_out;                    // [3,4096,4096] fp32

    dim3 vgrid(W_IMG / 4 / 128, H_IMG / VROWS, C_IMG);   // (8, 256, 3)
    vblur_kernel<<<vgrid, 128>>>((const float4*)img);

    dim3 hgrid(H_IMG, C_IMG);                            // (4096, 3)
    hblur_kernel<<<hgrid, 256>>>(out);
}